// round 7
// baseline (speedup 1.0000x reference)
#include <cuda_runtime.h>
#include <cstdint>

#define NN 50000
#define DD 64
#define NE 800000

// ---- scratch (__device__ globals; allocation-free rule) ----
__device__ int   g_csrc[NE];     // CSR: source node per edge, grouped by dst
__device__ int   g_deg[NN];      // invariant: zero at entry of every call
__device__ int   g_off[NN + 1];
__device__ int   g_cur[NN];
__device__ int   g_bsum[256];
__device__ int   g_done;         // invariant: zero at entry of every call
__device__ __align__(16) float g_t[NN * DD];   // t = act(X) @ W_nbr
__device__ __align__(16) float g_h[NN * DD];   // hidden activations

// ---------------------------------------------------------------------------
// Per-block int64-vs-int32 detection: sample the first 256 odd 32-bit words.
// int64 little-endian high halves (indices < 50000) are all zero; for int32
// they are real indices (P[all 256 zero] ~ (2e-5)^256 ~ 0).
// ---------------------------------------------------------------------------
__device__ __forceinline__ int detect_idx64(const unsigned* words) {
    __shared__ int nz;
    if (threadIdx.x == 0) nz = 0;
    __syncthreads();
    if (threadIdx.x < 256 && words[2 * threadIdx.x + 1] != 0u) nz = 1;
    __syncthreads();
    return nz ? 0 : 1;
}

// load 4 consecutive indices starting at elem i (16B-aligned when i%4==0)
__device__ __forceinline__ void load_idx4(const void* idx, size_t base, int idx64, int out[4]) {
    if (idx64) {
        const longlong2* p = (const longlong2*)((const long long*)idx + base);
        longlong2 a = p[0], b = p[1];
        out[0] = (int)a.x; out[1] = (int)a.y; out[2] = (int)b.x; out[3] = (int)b.y;
    } else {
        int4 v = *(const int4*)((const int*)idx + base);
        out[0] = v.x; out[1] = v.y; out[2] = v.z; out[3] = v.w;
    }
}

// histogram of dst degrees — 4 edges/thread for MLP on the L2 atomics
__global__ void hist_kernel(const void* __restrict__ idx, int E) {
    int idx64 = detect_idx64((const unsigned*)idx);
    int base = (blockIdx.x * blockDim.x + threadIdx.x) * 4;
    if (base >= E) return;
    if (base + 4 <= E) {
        int d[4];
        load_idx4(idx, (size_t)E + base, idx64, d);
#pragma unroll
        for (int k = 0; k < 4; k++) atomicAdd(&g_deg[d[k]], 1);
    } else {
        for (int e = base; e < E; e++) {
            int d = idx64 ? (int)((const long long*)idx)[(size_t)E + e]
                          : ((const int*)idx)[(size_t)E + e];
            atomicAdd(&g_deg[d], 1);
        }
    }
}

// ---- scan phase 1 (+ fused phase 2 via last-done block) ----
__global__ void scan1_kernel(int nblocks) {
    __shared__ int sh[256];
    int tid = threadIdx.x;
    int i = blockIdx.x * 256 + tid;
    int v = (i < NN) ? g_deg[i] : 0;
    sh[tid] = v;
    __syncthreads();
#pragma unroll
    for (int off = 1; off < 256; off <<= 1) {
        int x = (tid >= off) ? sh[tid - off] : 0;
        __syncthreads();
        sh[tid] += x;
        __syncthreads();
    }
    if (i < NN) g_off[i] = sh[tid] - v;          // exclusive within block
    if (tid == 255) g_bsum[blockIdx.x] = sh[255];

    // last-arriving block scans the block sums (exclusive) in-place
    __shared__ int is_last;
    __threadfence();
    if (tid == 0) is_last = (atomicAdd(&g_done, 1) == nblocks - 1) ? 1 : 0;
    __syncthreads();
    if (is_last) {
        int bv = (tid < nblocks) ? g_bsum[tid] : 0;
        sh[tid] = bv;
        __syncthreads();
#pragma unroll
        for (int off = 1; off < 256; off <<= 1) {
            int x = (tid >= off) ? sh[tid - off] : 0;
            __syncthreads();
            sh[tid] += x;
            __syncthreads();
        }
        if (tid < nblocks) g_bsum[tid] = sh[tid] - bv;
    }
}

// add block offsets; also restore g_deg=0 and g_done=0 for the next call
__global__ void scan3_kernel() {
    int i = blockIdx.x * 256 + threadIdx.x;
    if (i < NN) {
        int o = g_off[i] + g_bsum[blockIdx.x];
        g_off[i] = o;
        g_cur[i] = o;
        g_deg[i] = 0;
    }
    if (i == 0) { g_off[NN] = NE; g_done = 0; }
}

// fill CSR source list — 4 edges/thread for MLP on atomics + scattered stores
__global__ void fill_kernel(const void* __restrict__ idx, int E) {
    int idx64 = detect_idx64((const unsigned*)idx);
    int base = (blockIdx.x * blockDim.x + threadIdx.x) * 4;
    if (base >= E) return;
    if (base + 4 <= E) {
        int s[4], d[4], pos[4];
        load_idx4(idx, (size_t)base, idx64, s);
        load_idx4(idx, (size_t)E + base, idx64, d);
#pragma unroll
        for (int k = 0; k < 4; k++) pos[k] = atomicAdd(&g_cur[d[k]], 1);
#pragma unroll
        for (int k = 0; k < 4; k++) g_csrc[pos[k]] = s[k];
    } else {
        for (int e = base; e < E; e++) {
            int s, d;
            if (idx64) {
                s = (int)((const long long*)idx)[e];
                d = (int)((const long long*)idx)[(size_t)E + e];
            } else {
                s = ((const int*)idx)[e];
                d = ((const int*)idx)[(size_t)E + e];
            }
            g_csrc[atomicAdd(&g_cur[d], 1)] = s;
        }
    }
}

// ---------------------------------------------------------------------------
// Dual GEMM: Omain = act(X)@Wroot + b ; Ot = act(X)@Wnbr
// 128 rows/block, 256 threads. Thread tile: 4 rows x 8 cols x 2 matrices.
// X staged TRANSPOSED (sXT[k][r], stride 132 -> every float4 read 16B-aligned).
// ---------------------------------------------------------------------------
#define XT_STRIDE 132

template <bool RELU>
__global__ void __launch_bounds__(256, 2) gemm_dual_kernel(
    const float* __restrict__ X,
    const float* __restrict__ Wroot,
    const float* __restrict__ Wnbr,
    const float* __restrict__ bias,
    float* __restrict__ Omain,
    float* __restrict__ Ot,
    int n)
{
    __shared__ __align__(16) float sWr[64 * 64];
    __shared__ __align__(16) float sWn[64 * 64];
    __shared__ __align__(16) float sB[64];
    __shared__ __align__(16) float sXT[64 * XT_STRIDE];   // [k][row]

    const int tid = threadIdx.x;
    const int row0 = blockIdx.x * 128;

    // stage weights (1024 float4 each -> 4 per thread)
    {
        const float4* wr4 = (const float4*)Wroot;
        const float4* wn4 = (const float4*)Wnbr;
        float4* swr4 = (float4*)sWr;
        float4* swn4 = (float4*)sWn;
#pragma unroll
        for (int i = 0; i < 4; i++) {
            swr4[tid + 256 * i] = wr4[tid + 256 * i];
            swn4[tid + 256 * i] = wn4[tid + 256 * i];
        }
        if (tid < 64) sB[tid] = bias[tid];
    }

    // stage X transposed: 128 rows x 16 float4-chunks = 2048 chunks, 8/thread
#pragma unroll
    for (int i = 0; i < 8; i++) {
        int idx = tid + 256 * i;      // 0..2047
        int r = idx >> 4;             // local row 0..127
        int c4 = idx & 15;            // float4 chunk 0..15
        int grow = row0 + r;
        float4 v = make_float4(0.f, 0.f, 0.f, 0.f);
        if (grow < n) v = ((const float4*)X)[(size_t)grow * 16 + c4];
        if (RELU) {
            v.x = fmaxf(v.x, 0.f); v.y = fmaxf(v.y, 0.f);
            v.z = fmaxf(v.z, 0.f); v.w = fmaxf(v.w, 0.f);
        }
        sXT[(c4 * 4 + 0) * XT_STRIDE + r] = v.x;
        sXT[(c4 * 4 + 1) * XT_STRIDE + r] = v.y;
        sXT[(c4 * 4 + 2) * XT_STRIDE + r] = v.z;
        sXT[(c4 * 4 + 3) * XT_STRIDE + r] = v.w;
    }
    __syncthreads();

    const int cseg = tid & 7;        // cols [cseg*8, cseg*8+8)
    const int rowgrp = tid >> 3;     // rows [rowgrp*4, rowgrp*4+4)

    float4 ar[4][2], an[4][2];
    {
        float4 b0 = *(const float4*)&sB[cseg * 8];
        float4 b1 = *(const float4*)&sB[cseg * 8 + 4];
#pragma unroll
        for (int j = 0; j < 4; j++) {
            ar[j][0] = b0; ar[j][1] = b1;
            an[j][0] = make_float4(0.f, 0.f, 0.f, 0.f);
            an[j][1] = make_float4(0.f, 0.f, 0.f, 0.f);
        }
    }

#pragma unroll 8
    for (int k = 0; k < 64; k++) {
        float4 xv = *(const float4*)&sXT[k * XT_STRIDE + rowgrp * 4];
        float4 wr0 = *(const float4*)&sWr[k * 64 + cseg * 8];
        float4 wr1 = *(const float4*)&sWr[k * 64 + cseg * 8 + 4];
        float4 wn0 = *(const float4*)&sWn[k * 64 + cseg * 8];
        float4 wn1 = *(const float4*)&sWn[k * 64 + cseg * 8 + 4];
        const float xs[4] = {xv.x, xv.y, xv.z, xv.w};
#pragma unroll
        for (int j = 0; j < 4; j++) {
            float xvj = xs[j];
            ar[j][0].x = fmaf(xvj, wr0.x, ar[j][0].x);
            ar[j][0].y = fmaf(xvj, wr0.y, ar[j][0].y);
            ar[j][0].z = fmaf(xvj, wr0.z, ar[j][0].z);
            ar[j][0].w = fmaf(xvj, wr0.w, ar[j][0].w);
            ar[j][1].x = fmaf(xvj, wr1.x, ar[j][1].x);
            ar[j][1].y = fmaf(xvj, wr1.y, ar[j][1].y);
            ar[j][1].z = fmaf(xvj, wr1.z, ar[j][1].z);
            ar[j][1].w = fmaf(xvj, wr1.w, ar[j][1].w);
            an[j][0].x = fmaf(xvj, wn0.x, an[j][0].x);
            an[j][0].y = fmaf(xvj, wn0.y, an[j][0].y);
            an[j][0].z = fmaf(xvj, wn0.z, an[j][0].z);
            an[j][0].w = fmaf(xvj, wn0.w, an[j][0].w);
            an[j][1].x = fmaf(xvj, wn1.x, an[j][1].x);
            an[j][1].y = fmaf(xvj, wn1.y, an[j][1].y);
            an[j][1].z = fmaf(xvj, wn1.z, an[j][1].z);
            an[j][1].w = fmaf(xvj, wn1.w, an[j][1].w);
        }
    }

#pragma unroll
    for (int j = 0; j < 4; j++) {
        int grow = row0 + rowgrp * 4 + j;
        if (grow < n) {
            float4* om = (float4*)(Omain + (size_t)grow * 64 + cseg * 8);
            om[0] = ar[j][0]; om[1] = ar[j][1];
            float4* ot = (float4*)(Ot + (size_t)grow * 64 + cseg * 8);
            ot[0] = an[j][0]; ot[1] = an[j][1];
        }
    }
}

// ---------------------------------------------------------------------------
// CSR gather-aggregate: HALF-WARP per node, float4 per lane (16 x 16B = row).
// out[i] += sum_{e: dst==i} t[csrc[e]]
// ---------------------------------------------------------------------------
__global__ void __launch_bounds__(256) agg_kernel(
    const float* __restrict__ t, float* __restrict__ out, int n)
{
    int gid = blockIdx.x * blockDim.x + threadIdx.x;
    int node = gid >> 4;
    if (node >= n) return;
    int part = threadIdx.x & 15;

    int start = g_off[node];
    int end   = g_off[node + 1];

    const float4* t4 = (const float4*)t;
    float4 acc = make_float4(0.f, 0.f, 0.f, 0.f);

    int j = start;
    for (; j + 4 <= end; j += 4) {
        int s0 = __ldg(&g_csrc[j]);
        int s1 = __ldg(&g_csrc[j + 1]);
        int s2 = __ldg(&g_csrc[j + 2]);
        int s3 = __ldg(&g_csrc[j + 3]);
        float4 v0 = t4[(size_t)s0 * 16 + part];
        float4 v1 = t4[(size_t)s1 * 16 + part];
        float4 v2 = t4[(size_t)s2 * 16 + part];
        float4 v3 = t4[(size_t)s3 * 16 + part];
        acc.x += (v0.x + v1.x) + (v2.x + v3.x);
        acc.y += (v0.y + v1.y) + (v2.y + v3.y);
        acc.z += (v0.z + v1.z) + (v2.z + v3.z);
        acc.w += (v0.w + v1.w) + (v2.w + v3.w);
    }
    for (; j < end; j++) {
        int s = __ldg(&g_csrc[j]);
        float4 v = t4[(size_t)s * 16 + part];
        acc.x += v.x; acc.y += v.y; acc.z += v.z; acc.w += v.w;
    }

    float4* o4 = (float4*)out;
    float4 cur = o4[(size_t)node * 16 + part];
    cur.x += acc.x; cur.y += acc.y; cur.z += acc.z; cur.w += acc.w;
    o4[(size_t)node * 16 + part] = cur;
}

// ---------------------------------------------------------------------------
extern "C" void kernel_launch(void* const* d_in, const int* in_sizes, int n_in,
                              void* d_out, int out_size)
{
    const float* x      = (const float*)d_in[0];
    const void*  eidx   = d_in[1];
    const float* W1root = (const float*)d_in[2];
    const float* W1nbr  = (const float*)d_in[3];
    const float* b1     = (const float*)d_in[4];
    const float* W2root = (const float*)d_in[5];
    const float* W2nbr  = (const float*)d_in[6];
    const float* b2     = (const float*)d_in[7];
    float* out = (float*)d_out;

    const int n = in_sizes[0] / DD;     // 50000
    const int E = in_sizes[1] / 2;      // 800000

    float *hptr, *tptr;
    cudaGetSymbolAddress((void**)&hptr, g_h);
    cudaGetSymbolAddress((void**)&tptr, g_t);

    const int edge4_blocks = (E / 4 + 255) / 256;     // 4 edges per thread
    const int scan_blocks = (n + 255) / 256;          // 196
    const int gemm_blocks = (n + 127) / 128;
    const int agg_blocks  = (n * 16 + 255) / 256;

    // Side stream + events for graph-level parallelism (host-side resources
    // only; created once, reused — identical captured work every call).
    static cudaStream_t s_side = nullptr;
    static cudaEvent_t  ev_fork = nullptr, ev_join = nullptr;
    if (s_side == nullptr) {
        cudaStreamCreateWithFlags(&s_side, cudaStreamNonBlocking);
        cudaEventCreateWithFlags(&ev_fork, cudaEventDisableTiming);
        cudaEventCreateWithFlags(&ev_join, cudaEventDisableTiming);
    }

    // ---- fork: CSR build on side stream, concurrent with gemm1 ----
    cudaEventRecord(ev_fork, cudaStreamPerThread);
    cudaStreamWaitEvent(s_side, ev_fork, 0);

    hist_kernel <<<edge4_blocks, 256, 0, s_side>>>(eidx, E);
    scan1_kernel<<<scan_blocks, 256, 0, s_side>>>(scan_blocks);
    scan3_kernel<<<scan_blocks, 256, 0, s_side>>>();
    fill_kernel <<<edge4_blocks, 256, 0, s_side>>>(eidx, E);
    cudaEventRecord(ev_join, s_side);

    // ---- main stream: layer-1 GEMM in parallel with CSR build ----
    gemm_dual_kernel<false><<<gemm_blocks, 256>>>(x, W1root, W1nbr, b1, hptr, tptr, n);

    // join: agg1 needs both CSR and t1
    cudaStreamWaitEvent(cudaStreamPerThread, ev_join, 0);
    agg_kernel<<<agg_blocks, 256>>>(tptr, hptr, n);

    // ---- Layer 2 ----
    gemm_dual_kernel<true><<<gemm_blocks, 256>>>(hptr, W2root, W2nbr, b2, out, tptr, n);
    agg_kernel<<<agg_blocks, 256>>>(tptr, out, n);
}